// round 1
// baseline (speedup 1.0000x reference)
#include <cuda_runtime.h>
#include <math.h>

#define BSZ 16
#define SEQ 2048
#define HID 1024
#define NSP_PER_B 32
#define NCLS 8
#define NLBL 3
#define NSPAN (BSZ * NSP_PER_B)   // 512
#define H4 (HID / 4)              // 256

// One CTA per span: mean-pool 63 rows of encoder over H, then dot with
// W[c,:,0..2], add bias, write 3 logits.
__global__ __launch_bounds__(256, 4)
void span_logits_kernel(const float* __restrict__ enc,
                        const float* __restrict__ W,
                        const float* __restrict__ bias,
                        const int* __restrict__ head,
                        const int* __restrict__ tail,
                        const int* __restrict__ cls,
                        float* __restrict__ logits)
{
    const int span = blockIdx.x;            // 0..511
    const int b    = span / NSP_PER_B;
    const int s0   = head[span] + 1;
    const int n    = tail[span] - s0;       // span length (63 here)
    const int c    = cls[span];
    const int tid  = threadIdx.x;           // 256 threads, 4 H-cols each

    const float4* base = reinterpret_cast<const float4*>(enc)
                       + ((long)b * SEQ + s0) * H4 + tid;

    float4 a0 = make_float4(0.f, 0.f, 0.f, 0.f);
    float4 a1 = a0, a2 = a0, a3 = a0;
    int s = 0;
    for (; s + 4 <= n; s += 4) {
        float4 v0 = base[(s + 0) * H4];
        float4 v1 = base[(s + 1) * H4];
        float4 v2 = base[(s + 2) * H4];
        float4 v3 = base[(s + 3) * H4];
        a0.x += v0.x; a0.y += v0.y; a0.z += v0.z; a0.w += v0.w;
        a1.x += v1.x; a1.y += v1.y; a1.z += v1.z; a1.w += v1.w;
        a2.x += v2.x; a2.y += v2.y; a2.z += v2.z; a2.w += v2.w;
        a3.x += v3.x; a3.y += v3.y; a3.z += v3.z; a3.w += v3.w;
    }
    for (; s < n; ++s) {
        float4 v = base[s * H4];
        a0.x += v.x; a0.y += v.y; a0.z += v.z; a0.w += v.w;
    }
    float4 acc;
    acc.x = (a0.x + a1.x) + (a2.x + a3.x);
    acc.y = (a0.y + a1.y) + (a2.y + a3.y);
    acc.z = (a0.z + a1.z) + (a2.z + a3.z);
    acc.w = (a0.w + a1.w) + (a2.w + a3.w);

    // W is (C, H, L): the 4 columns this thread owns are 12 contiguous floats.
    const float4* w4 = reinterpret_cast<const float4*>(W + (long)c * HID * NLBL)
                     + tid * 3;
    float4 w0 = w4[0], w1 = w4[1], w2 = w4[2];
    // layout: h:[l0 l1 l2] h+1:[l0 l1 l2] h+2:[l0 l1 l2] h+3:[l0 l1 l2]
    float p0 = acc.x * w0.x + acc.y * w0.w + acc.z * w1.z + acc.w * w2.y;
    float p1 = acc.x * w0.y + acc.y * w1.x + acc.z * w1.w + acc.w * w2.z;
    float p2 = acc.x * w0.z + acc.y * w1.y + acc.z * w2.x + acc.w * w2.w;

    // block reduction: warp shuffle then 8-warp smem combine
    #pragma unroll
    for (int off = 16; off > 0; off >>= 1) {
        p0 += __shfl_down_sync(0xffffffffu, p0, off);
        p1 += __shfl_down_sync(0xffffffffu, p1, off);
        p2 += __shfl_down_sync(0xffffffffu, p2, off);
    }
    __shared__ float sm[3][8];
    const int warp = tid >> 5, lane = tid & 31;
    if (lane == 0) { sm[0][warp] = p0; sm[1][warp] = p1; sm[2][warp] = p2; }
    __syncthreads();
    if (tid < NLBL) {
        float t = 0.f;
        #pragma unroll
        for (int w = 0; w < 8; ++w) t += sm[tid][w];
        float inv = 1.0f / (float)n;
        logits[span * NLBL + tid] = t * inv + bias[c * NLBL + tid];
    }
}

// One block: per-span 3-way log-softmax NLL, masked mean -> out[NSPAN*NLBL].
__global__ __launch_bounds__(512, 1)
void loss_kernel(const float* __restrict__ logits,
                 const int* __restrict__ labels,
                 float* __restrict__ out)
{
    const int i = threadIdx.x;   // 512 == NSPAN
    float nll = 0.f, vf = 0.f;
    float l0 = logits[i * 3 + 0];
    float l1 = logits[i * 3 + 1];
    float l2 = logits[i * 3 + 2];
    int lab = labels[i];
    if (lab >= 0) {
        float m   = fmaxf(l0, fmaxf(l1, l2));
        float lse = m + logf(expf(l0 - m) + expf(l1 - m) + expf(l2 - m));
        float lv  = (lab == 0) ? l0 : ((lab == 1) ? l1 : l2);
        nll = lse - lv;
        vf  = 1.f;
    }
    #pragma unroll
    for (int off = 16; off > 0; off >>= 1) {
        nll += __shfl_down_sync(0xffffffffu, nll, off);
        vf  += __shfl_down_sync(0xffffffffu, vf,  off);
    }
    __shared__ float sn[16], sv[16];
    const int warp = i >> 5, lane = i & 31;
    if (lane == 0) { sn[warp] = nll; sv[warp] = vf; }
    __syncthreads();
    if (i == 0) {
        float tn = 0.f, tv = 0.f;
        #pragma unroll
        for (int w = 0; w < 16; ++w) { tn += sn[w]; tv += sv[w]; }
        out[NSPAN * NLBL] = tn / tv;
    }
}

extern "C" void kernel_launch(void* const* d_in, const int* in_sizes, int n_in,
                              void* d_out, int out_size)
{
    const float* enc  = (const float*)d_in[0];   // (16,2048,1024)
    const float* W    = (const float*)d_in[1];   // (8,1024,3)
    const float* bias = (const float*)d_in[2];   // (8,3)
    const int*   head = (const int*)d_in[3];     // (16,32)
    const int*   tail = (const int*)d_in[4];     // (16,32)
    const int*   cls  = (const int*)d_in[5];     // (16,32)
    const int*   lab  = (const int*)d_in[6];     // (16,32)
    float* out = (float*)d_out;                  // logits (512*3) then loss

    span_logits_kernel<<<NSPAN, 256>>>(enc, W, bias, head, tail, cls, out);
    if (out_size > NSPAN * NLBL) {
        loss_kernel<<<1, 512>>>(out, lab, out);
    }
}